// round 2
// baseline (speedup 1.0000x reference)
#include <cuda_runtime.h>

#define HH 512
#define WW 1024
#define HWSZ (HH*WW)

// Scratch (device globals; allocation in kernel_launch is forbidden)
__device__ float g_bufA[100 * HWSZ];          // ~210 MB
__device__ float g_bufB[100 * HWSZ];          // ~210 MB
__device__ float g_part[21 * 4 * HWSZ];       // ~176 MB per-patch-row partials (r,g,b,sum)

// ---------------------------------------------------------------------------
// 3x3 SAME conv, register-tiled: block = 20 oc x (32x16) px, 320 threads.
// Each thread: 4 oc x 8 px (32 fp32 accumulators). Input staged in smem in
// chunks of 10 channels, row stride 35 (bank-conflict-free for ty0..7 x tx0..3
// warps). Weights staged as [ic][k][oc20], read as float4 broadcast.
// ---------------------------------------------------------------------------
template<int CIN, bool RELU>
__global__ __launch_bounds__(320)
void conv3x3_k(const float* __restrict__ in, const float* __restrict__ w,
               const float* __restrict__ b, float* __restrict__ out)
{
    constexpr int ICC = 10;
    constexpr int OCB = 20;
    __shared__ __align__(16) float s_in[ICC][18][35];
    __shared__ __align__(16) float s_w[ICC][9][OCB];

    const int tid = threadIdx.x;
    const int ocg = tid >> 6;      // 0..4
    const int r   = tid & 63;
    const int ty  = r >> 2;        // 0..15
    const int tx  = r & 3;         // 0..3
    const int x0  = blockIdx.x * 32;
    const int y0  = blockIdx.y * 16;
    const int ocb = blockIdx.z * OCB;

    float acc[4][8];
    #pragma unroll
    for (int j = 0; j < 4; j++) {
        const float bv = b[ocb + ocg * 4 + j];
        #pragma unroll
        for (int p = 0; p < 8; p++) acc[j][p] = bv;
    }

    for (int icc = 0; icc < CIN; icc += ICC) {
        __syncthreads();
        // stage input tile (+halo), zero-padded
        for (int idx = tid; idx < ICC * 18 * 34; idx += 320) {
            const int xx = idx % 34;
            const int t1 = idx / 34;
            const int yy = t1 % 18;
            const int ic = t1 / 18;
            const int gy = y0 + yy - 1, gx = x0 + xx - 1;
            float v = 0.f;
            if ((unsigned)gy < HH && (unsigned)gx < WW)
                v = in[(size_t)(icc + ic) * HWSZ + gy * WW + gx];
            s_in[ic][yy][xx] = v;
        }
        // stage weights [ic][k][oc]
        for (int idx = tid; idx < ICC * 9 * OCB; idx += 320) {
            const int oc = idx % OCB;
            const int t1 = idx / OCB;
            const int k  = t1 % 9;
            const int ic = t1 / 9;
            s_w[ic][k][oc] = w[(size_t)(ocb + oc) * (CIN * 9) + (icc + ic) * 9 + k];
        }
        __syncthreads();

        for (int ic = 0; ic < ICC; ic++) {
            const float* prow0 = &s_in[ic][ty][tx * 8];
            const float* pwic  = &s_w[ic][0][ocg * 4];
            #pragma unroll
            for (int ky = 0; ky < 3; ky++) {
                const float* prow = prow0 + ky * 35;
                float rr[10];
                #pragma unroll
                for (int j = 0; j < 10; j++) rr[j] = prow[j];
                #pragma unroll
                for (int kx = 0; kx < 3; kx++) {
                    const float4 wv = *(const float4*)(pwic + (ky * 3 + kx) * OCB);
                    #pragma unroll
                    for (int p = 0; p < 8; p++) {
                        const float iv = rr[p + kx];
                        acc[0][p] = fmaf(wv.x, iv, acc[0][p]);
                        acc[1][p] = fmaf(wv.y, iv, acc[1][p]);
                        acc[2][p] = fmaf(wv.z, iv, acc[2][p]);
                        acc[3][p] = fmaf(wv.w, iv, acc[3][p]);
                    }
                }
            }
        }
    }

    // store (2x float4 per oc), optional LeakyReLU(0.01)
    #pragma unroll
    for (int j = 0; j < 4; j++) {
        float* po = out + (size_t)(ocb + ocg * 4 + j) * HWSZ + (y0 + ty) * WW + x0 + tx * 8;
        float v[8];
        #pragma unroll
        for (int p = 0; p < 8; p++) {
            float x = acc[j][p];
            if (RELU) x = (x > 0.f) ? x : 0.01f * x;
            v[p] = x;
        }
        *(float4*)po       = make_float4(v[0], v[1], v[2], v[3]);
        *(float4*)(po + 4) = make_float4(v[4], v[5], v[6], v[7]);
    }
}

// ---------------------------------------------------------------------------
// conv_last (100 -> 441) fused with kernel regression, one patch row per
// z-block (dy = blockIdx.z, oc = dy*21 .. dy*21+20, so oc%21 = dx).
// Block = 21 oc x (32x8) px, 224 threads (7 oc-groups x 32 px-threads).
// Writes deterministic per-(row) partials: g_part[(z*4+c)*HW + px].
// ---------------------------------------------------------------------------
__global__ __launch_bounds__(224)
void convlast_k(const float* __restrict__ feat, const float* __restrict__ rgb,
                const float* __restrict__ w, const float* __restrict__ b)
{
    constexpr int ICC = 5;
    constexpr int OCB = 21;
    __shared__ __align__(16) float s_in[ICC][10][35];
    __shared__ float s_w[ICC][9][OCB];
    __shared__ float s_rgb[3][8][52];
    __shared__ float s_red[7][8][32][4];

    const int tid = threadIdx.x;
    const int g   = tid >> 5;      // 0..6
    const int r   = tid & 31;
    const int ty  = r >> 2;        // 0..7
    const int tx  = r & 3;         // 0..3
    const int x0  = blockIdx.x * 32;
    const int y0  = blockIdx.y * 8;
    const int z   = blockIdx.z;    // dy (patch row)
    const int ocb = z * OCB;

    // stage rgb tile for this dy: rows y0+ty+z-10, cols x0-10 .. x0+41
    for (int idx = tid; idx < 3 * 8 * 52; idx += 224) {
        const int xx = idx % 52;
        const int t1 = idx / 52;
        const int yy = t1 % 8;
        const int c  = t1 / 8;
        const int gy = y0 + yy + z - 10;
        const int gx = x0 + xx - 10;
        float v = 0.f;
        if ((unsigned)gy < HH && (unsigned)gx < WW)
            v = rgb[(size_t)c * HWSZ + gy * WW + gx];
        s_rgb[c][yy][xx] = v;
    }

    float acc[3][8];
    #pragma unroll
    for (int j = 0; j < 3; j++) {
        const float bv = b[ocb + g * 3 + j];
        #pragma unroll
        for (int p = 0; p < 8; p++) acc[j][p] = bv;
    }

    for (int icc = 0; icc < 100; icc += ICC) {
        __syncthreads();
        for (int idx = tid; idx < ICC * 10 * 34; idx += 224) {
            const int xx = idx % 34;
            const int t1 = idx / 34;
            const int yy = t1 % 10;
            const int ic = t1 / 10;
            const int gy = y0 + yy - 1, gx = x0 + xx - 1;
            float v = 0.f;
            if ((unsigned)gy < HH && (unsigned)gx < WW)
                v = feat[(size_t)(icc + ic) * HWSZ + gy * WW + gx];
            s_in[ic][yy][xx] = v;
        }
        for (int idx = tid; idx < ICC * 9 * OCB; idx += 224) {
            const int oc = idx % OCB;
            const int t1 = idx / OCB;
            const int k  = t1 % 9;
            const int ic = t1 / 9;
            s_w[ic][k][oc] = w[(size_t)(ocb + oc) * 900 + (icc + ic) * 9 + k];
        }
        __syncthreads();

        for (int ic = 0; ic < ICC; ic++) {
            const float* prow0 = &s_in[ic][ty][tx * 8];
            #pragma unroll
            for (int ky = 0; ky < 3; ky++) {
                const float* prow = prow0 + ky * 35;
                float rr[10];
                #pragma unroll
                for (int j = 0; j < 10; j++) rr[j] = prow[j];
                #pragma unroll
                for (int kx = 0; kx < 3; kx++) {
                    const float* wp = &s_w[ic][ky * 3 + kx][g * 3];
                    const float w0 = wp[0], w1 = wp[1], w2 = wp[2];
                    #pragma unroll
                    for (int p = 0; p < 8; p++) {
                        const float iv = rr[p + kx];
                        acc[0][p] = fmaf(w0, iv, acc[0][p]);
                        acc[1][p] = fmaf(w1, iv, acc[1][p]);
                        acc[2][p] = fmaf(w2, iv, acc[2][p]);
                    }
                }
            }
        }
    }

    // per-thread partial (3 oc of this patch row), dx = g*3 + j
    const int d0 = g * 3;
    #pragma unroll
    for (int p = 0; p < 8; p++) {
        const int col = tx * 8 + p;
        const float a0 = acc[0][p], a1 = acc[1][p], a2 = acc[2][p];
        const float ssum = a0 + a1 + a2;
        const float pr = a0 * s_rgb[0][ty][col + d0] + a1 * s_rgb[0][ty][col + d0 + 1] + a2 * s_rgb[0][ty][col + d0 + 2];
        const float pg = a0 * s_rgb[1][ty][col + d0] + a1 * s_rgb[1][ty][col + d0 + 1] + a2 * s_rgb[1][ty][col + d0 + 2];
        const float pb = a0 * s_rgb[2][ty][col + d0] + a1 * s_rgb[2][ty][col + d0 + 1] + a2 * s_rgb[2][ty][col + d0 + 2];
        s_red[g][ty][col][0] = pr;
        s_red[g][ty][col][1] = pg;
        s_red[g][ty][col][2] = pb;
        s_red[g][ty][col][3] = ssum;
    }
    __syncthreads();

    // deterministic within-block reduction over the 7 oc-groups, then write
    for (int idx = tid; idx < 8 * 32 * 4; idx += 224) {
        const int c   = idx & 3;
        const int col = (idx >> 2) & 31;
        const int yy  = idx >> 7;
        float v = 0.f;
        #pragma unroll
        for (int gg = 0; gg < 7; gg++) v += s_red[gg][yy][col][c];
        g_part[(size_t)(z * 4 + c) * HWSZ + (y0 + yy) * WW + x0 + col] = v;
    }
}

// ---------------------------------------------------------------------------
// Sum the 21 patch-row partials (fixed order -> deterministic), normalize.
// out[c][i] = rgb_acc[c] / (sum + 1e-6)
// ---------------------------------------------------------------------------
__global__ __launch_bounds__(256)
void finalize_k(float* __restrict__ out)
{
    const int i = blockIdx.x * blockDim.x + threadIdx.x;
    if (i >= HWSZ) return;
    float sr = 0.f, sg = 0.f, sb = 0.f, ss = 0.f;
    for (int zz = 0; zz < 21; zz++) {
        const float* p = g_part + (size_t)(zz * 4) * HWSZ + i;
        sr += p[0];
        sg += p[(size_t)HWSZ];
        sb += p[(size_t)2 * HWSZ];
        ss += p[(size_t)3 * HWSZ];
    }
    const float inv = 1.f / (ss + 1e-6f);
    out[i]                    = sr * inv;
    out[(size_t)HWSZ + i]     = sg * inv;
    out[(size_t)2 * HWSZ + i] = sb * inv;
}

// ---------------------------------------------------------------------------
// inputs (metadata order): input, ref(unused), w0, b0, w_mid, b_mid, w_last, b_last
// ---------------------------------------------------------------------------
extern "C" void kernel_launch(void* const* d_in, const int* in_sizes, int n_in,
                              void* d_out, int out_size)
{
    const float* input  = (const float*)d_in[0];
    const float* w0     = (const float*)d_in[2];
    const float* b0     = (const float*)d_in[3];
    const float* w_mid  = (const float*)d_in[4];
    const float* b_mid  = (const float*)d_in[5];
    const float* w_last = (const float*)d_in[6];
    const float* b_last = (const float*)d_in[7];
    float* out = (float*)d_out;

    float *A, *B;
    cudaGetSymbolAddress((void**)&A, g_bufA);
    cudaGetSymbolAddress((void**)&B, g_bufB);

    const dim3 gc(WW / 32, HH / 16, 5);   // (32, 32, 5): 100 oc in tiles of 20

    // layer 0: 10 -> 100, no activation
    conv3x3_k<10, false><<<gc, 320>>>(input, w0, b0, A);

    // 23 x (100 -> 100) + LeakyReLU(0.01), ping-pong
    const float* cur = A;
    float* nxt = B;
    for (int l = 0; l < 23; l++) {
        conv3x3_k<100, true><<<gc, 320>>>(cur, w_mid + (size_t)l * 90000,
                                          b_mid + (size_t)l * 100, nxt);
        float* t = (float*)cur; cur = nxt; nxt = t;
    }
    // after 23 swaps, features are in B (cur)

    // conv_last (100 -> 441) fused with kernel regression partials
    convlast_k<<<dim3(WW / 32, HH / 8, 21), 224>>>(cur, input, w_last, b_last);

    // reduce 21 rows + normalize
    finalize_k<<<(HWSZ + 255) / 256, 256>>>(out);
}

// round 3
// speedup vs baseline: 1.5776x; 1.5776x over previous
#include <cuda_runtime.h>

#define HH 512
#define WW 1024
#define HWSZ (HH*WW)

// Scratch (device globals; allocation in kernel_launch is forbidden)
__device__ float g_bufA[100 * HWSZ];
__device__ float g_bufB[100 * HWSZ];
__device__ float g_part[21 * 4 * HWSZ];

// ---------------- cp.async helpers ----------------
__device__ __forceinline__ unsigned smem_u32(const void* p) {
    unsigned a;
    asm("{ .reg .u64 t; cvta.to.shared.u64 t, %1; cvt.u32.u64 %0, t; }" : "=r"(a) : "l"(p));
    return a;
}
__device__ __forceinline__ void cpa4(unsigned dst, const void* src, int sz) {
    asm volatile("cp.async.ca.shared.global [%0], [%1], 4, %2;" :: "r"(dst), "l"(src), "r"(sz));
}
__device__ __forceinline__ void cpa_commit() { asm volatile("cp.async.commit_group;"); }
__device__ __forceinline__ void cpa_wait0()  { asm volatile("cp.async.wait_group 0;"); }

// ---------------------------------------------------------------------------
// 3x3 SAME conv: block = 20 oc x (32x16) px, 320 threads, 4oc x 8px / thread.
// cp.async double-buffered staging (10-ic chunks), stride-36 smem rows so the
// inner loop uses LDS.128 (conflict-free for this warp shape).
// smem layout (dynamic): s_in[2][10][18][36], s_w[2][10*9*20]
// ---------------------------------------------------------------------------
#define C3_SIN (2*10*18*36)
#define C3_SW  (2*10*9*20)
#define C3_SMEM ((C3_SIN + C3_SW)*4)

template<int CIN, bool RELU>
__global__ __launch_bounds__(320, 2)
void conv3x3_k(const float* __restrict__ in, const float* __restrict__ w,
               const float* __restrict__ b, float* __restrict__ out)
{
    constexpr int ICC = 10;
    constexpr int OCB = 20;
    constexpr int NCH = CIN / ICC;
    extern __shared__ float sm[];
    float* s_in = sm;              // [2][ICC][18][36]
    float* s_w  = sm + C3_SIN;     // [2][ICC*9*OCB]

    const int tid  = threadIdx.x;
    const int wrp  = tid >> 5;     // 0..9
    const int lane = tid & 31;
    const int ocg  = tid >> 6;     // 0..4
    const int r    = tid & 63;
    const int ty   = r >> 2;       // 0..15
    const int tx   = r & 3;        // 0..3
    const int x0   = blockIdx.x * 32;
    const int y0   = blockIdx.y * 16;
    const int ocb  = blockIdx.z * OCB;

    const unsigned sin_a = smem_u32(s_in);
    const unsigned sw_a  = smem_u32(s_w);

    // stage one 10-ic chunk (input tile + weights) into buffer bufi
    auto stage = [&](int icc, int bufi) {
        const float* inc = in + (size_t)(icc + wrp) * HWSZ;
        unsigned ib = sin_a + (unsigned)(bufi * ICC * 18 * 36 + wrp * 18 * 36) * 4u;
        #pragma unroll
        for (int yy = 0; yy < 18; yy++) {
            const int gy = y0 + yy - 1;
            const bool rowok = (unsigned)gy < HH;
            const float* rp = inc + (size_t)gy * WW;
            {
                const int gx = x0 + lane - 1;
                const bool ok = rowok && (unsigned)gx < WW;
                cpa4(ib + (unsigned)(yy * 36 + lane) * 4u, ok ? (rp + gx) : in, ok ? 4 : 0);
            }
            if (lane < 2) {
                const int gx = x0 + 31 + lane;
                const bool ok = rowok && (unsigned)gx < WW;
                cpa4(ib + (unsigned)(yy * 36 + 32 + lane) * 4u, ok ? (rp + gx) : in, ok ? 4 : 0);
            }
        }
        // weights: warp stages 2 ocs; 90 contiguous gmem floats per oc
        unsigned wb = sw_a + (unsigned)(bufi * ICC * 9 * OCB) * 4u;
        #pragma unroll
        for (int oo = 0; oo < 2; oo++) {
            const int ocl = wrp * 2 + oo;
            const float* wp = w + (size_t)(ocb + ocl) * (CIN * 9) + icc * 9;
            #pragma unroll
            for (int i = 0; i < 3; i++) {
                const int e = lane + i * 32;
                if (e < 90) cpa4(wb + (unsigned)(e * OCB + ocl) * 4u, wp + e, 4);
            }
        }
    };

    float acc[4][8];
    #pragma unroll
    for (int j = 0; j < 4; j++) {
        const float bv = b[ocb + ocg * 4 + j];
        #pragma unroll
        for (int p = 0; p < 8; p++) acc[j][p] = bv;
    }

    stage(0, 0);
    cpa_commit();

    for (int c = 0; c < NCH; c++) {
        cpa_wait0();
        __syncthreads();
        if (c + 1 < NCH) { stage((c + 1) * ICC, (c + 1) & 1); cpa_commit(); }

        const float* bi = s_in + (c & 1) * (ICC * 18 * 36);
        const float* bw = s_w  + (c & 1) * (ICC * 9 * OCB);
        #pragma unroll 2
        for (int ic = 0; ic < ICC; ic++) {
            const float* prow0 = bi + (ic * 18 + ty) * 36 + tx * 8;
            const float* pw    = bw + ic * 9 * OCB + ocg * 4;
            #pragma unroll
            for (int ky = 0; ky < 3; ky++) {
                const float* pr = prow0 + ky * 36;
                const float4 v0 = *(const float4*)pr;
                const float4 v1 = *(const float4*)(pr + 4);
                float rr[10];
                rr[0]=v0.x; rr[1]=v0.y; rr[2]=v0.z; rr[3]=v0.w;
                rr[4]=v1.x; rr[5]=v1.y; rr[6]=v1.z; rr[7]=v1.w;
                rr[8]=pr[8]; rr[9]=pr[9];
                #pragma unroll
                for (int kx = 0; kx < 3; kx++) {
                    const float4 wv = *(const float4*)(pw + (ky * 3 + kx) * OCB);
                    #pragma unroll
                    for (int p = 0; p < 8; p++) {
                        const float iv = rr[p + kx];
                        acc[0][p] = fmaf(wv.x, iv, acc[0][p]);
                        acc[1][p] = fmaf(wv.y, iv, acc[1][p]);
                        acc[2][p] = fmaf(wv.z, iv, acc[2][p]);
                        acc[3][p] = fmaf(wv.w, iv, acc[3][p]);
                    }
                }
            }
        }
    }

    #pragma unroll
    for (int j = 0; j < 4; j++) {
        float* po = out + (size_t)(ocb + ocg * 4 + j) * HWSZ + (y0 + ty) * WW + x0 + tx * 8;
        float v[8];
        #pragma unroll
        for (int p = 0; p < 8; p++) {
            float x = acc[j][p];
            if (RELU) x = (x > 0.f) ? x : 0.01f * x;
            v[p] = x;
        }
        *(float4*)po       = make_float4(v[0], v[1], v[2], v[3]);
        *(float4*)(po + 4) = make_float4(v[4], v[5], v[6], v[7]);
    }
}

// ---------------------------------------------------------------------------
// conv_last (100 -> 441) fused with kernel regression; dy = blockIdx.z.
// Block = 21 oc x (32x8) px, 224 threads (7 warps x 3 oc each).
// Same cp.async double-buffered pipeline, ICC=10.
// smem: s_in[2][10][10][36], s_w[2][10*9*21], s_rgb[3][8][52], s_red[7][8][32][4]
// ---------------------------------------------------------------------------
#define CL_SIN  (2*10*10*36)
#define CL_SW   (2*10*9*21)
#define CL_SRGB (3*8*52)
#define CL_SRED (7*8*32*4)
#define CL_SMEM ((CL_SIN + CL_SW + CL_SRGB + CL_SRED)*4)

__global__ __launch_bounds__(224, 2)
void convlast_k(const float* __restrict__ feat, const float* __restrict__ rgb,
                const float* __restrict__ w, const float* __restrict__ b)
{
    constexpr int ICC = 10;
    constexpr int OCB = 21;
    extern __shared__ float sm[];
    float* s_in  = sm;                          // [2][ICC][10][36]
    float* s_w   = sm + CL_SIN;                 // [2][ICC*9*21]
    float* s_rgb = sm + CL_SIN + CL_SW;         // [3][8][52]
    float* s_red = sm + CL_SIN + CL_SW + CL_SRGB; // [7][8][32][4]

    const int tid  = threadIdx.x;
    const int wrp  = tid >> 5;     // 0..6 (== oc group g)
    const int lane = tid & 31;
    const int g    = wrp;
    const int ty   = lane >> 2;    // 0..7
    const int tx   = lane & 3;     // 0..3
    const int x0   = blockIdx.x * 32;
    const int y0   = blockIdx.y * 8;
    const int z    = blockIdx.z;   // dy
    const int ocb  = z * OCB;

    const unsigned sin_a  = smem_u32(s_in);
    const unsigned sw_a   = smem_u32(s_w);
    const unsigned srgb_a = smem_u32(s_rgb);

    // stage rgb tile once (group 0, waited with chunk 0)
    for (int idx = tid; idx < 3 * 8 * 52; idx += 224) {
        const int xx = idx % 52;
        const int t1 = idx / 52;
        const int yy = t1 % 8;
        const int cc = t1 / 8;
        const int gy = y0 + yy + z - 10;
        const int gx = x0 + xx - 10;
        const bool ok = (unsigned)gy < HH && (unsigned)gx < WW;
        cpa4(srgb_a + (unsigned)idx * 4u,
             ok ? (rgb + (size_t)cc * HWSZ + gy * WW + gx) : rgb, ok ? 4 : 0);
    }

    auto stage = [&](int icc, int bufi) {
        unsigned ib = sin_a + (unsigned)(bufi * ICC * 10 * 36) * 4u;
        for (int rid = wrp; rid < 100; rid += 7) {
            const int ic = rid / 10;
            const int yy = rid - ic * 10;
            const int gy = y0 + yy - 1;
            const bool rowok = (unsigned)gy < HH;
            const float* rp = feat + (size_t)(icc + ic) * HWSZ + (size_t)gy * WW;
            {
                const int gx = x0 + lane - 1;
                const bool ok = rowok && (unsigned)gx < WW;
                cpa4(ib + (unsigned)((ic * 10 + yy) * 36 + lane) * 4u, ok ? (rp + gx) : feat, ok ? 4 : 0);
            }
            if (lane < 2) {
                const int gx = x0 + 31 + lane;
                const bool ok = rowok && (unsigned)gx < WW;
                cpa4(ib + (unsigned)((ic * 10 + yy) * 36 + 32 + lane) * 4u, ok ? (rp + gx) : feat, ok ? 4 : 0);
            }
        }
        unsigned wb = sw_a + (unsigned)(bufi * ICC * 9 * OCB) * 4u;
        #pragma unroll
        for (int oo = 0; oo < 3; oo++) {
            const int ocl = wrp * 3 + oo;
            const float* wp = w + (size_t)(ocb + ocl) * 900 + icc * 9;
            #pragma unroll
            for (int i = 0; i < 3; i++) {
                const int e = lane + i * 32;
                if (e < 90) cpa4(wb + (unsigned)(e * OCB + ocl) * 4u, wp + e, 4);
            }
        }
    };

    float acc[3][8];
    #pragma unroll
    for (int j = 0; j < 3; j++) {
        const float bv = b[ocb + g * 3 + j];
        #pragma unroll
        for (int p = 0; p < 8; p++) acc[j][p] = bv;
    }

    stage(0, 0);
    cpa_commit();

    for (int c = 0; c < 10; c++) {
        cpa_wait0();
        __syncthreads();
        if (c + 1 < 10) { stage((c + 1) * ICC, (c + 1) & 1); cpa_commit(); }

        const float* bi = s_in + (c & 1) * (ICC * 10 * 36);
        const float* bw = s_w  + (c & 1) * (ICC * 9 * OCB);
        #pragma unroll 2
        for (int ic = 0; ic < ICC; ic++) {
            const float* prow0 = bi + (ic * 10 + ty) * 36 + tx * 8;
            const float* pwic  = bw + ic * 9 * OCB + g * 3;
            #pragma unroll
            for (int ky = 0; ky < 3; ky++) {
                const float* pr = prow0 + ky * 36;
                const float4 v0 = *(const float4*)pr;
                const float4 v1 = *(const float4*)(pr + 4);
                float rr[10];
                rr[0]=v0.x; rr[1]=v0.y; rr[2]=v0.z; rr[3]=v0.w;
                rr[4]=v1.x; rr[5]=v1.y; rr[6]=v1.z; rr[7]=v1.w;
                rr[8]=pr[8]; rr[9]=pr[9];
                #pragma unroll
                for (int kx = 0; kx < 3; kx++) {
                    const float* wp = pwic + (ky * 3 + kx) * OCB;
                    const float w0 = wp[0], w1 = wp[1], w2 = wp[2];
                    #pragma unroll
                    for (int p = 0; p < 8; p++) {
                        const float iv = rr[p + kx];
                        acc[0][p] = fmaf(w0, iv, acc[0][p]);
                        acc[1][p] = fmaf(w1, iv, acc[1][p]);
                        acc[2][p] = fmaf(w2, iv, acc[2][p]);
                    }
                }
            }
        }
    }

    // per-thread partial (3 oc = dx g*3..g*3+2 of patch row z)
    const int d0 = g * 3;
    #pragma unroll
    for (int p = 0; p < 8; p++) {
        const int col = tx * 8 + p;
        const float a0 = acc[0][p], a1 = acc[1][p], a2 = acc[2][p];
        const float* r0 = s_rgb + (0 * 8 + ty) * 52 + col + d0;
        const float* r1 = s_rgb + (1 * 8 + ty) * 52 + col + d0;
        const float* r2 = s_rgb + (2 * 8 + ty) * 52 + col + d0;
        float* sr = s_red + ((g * 8 + ty) * 32 + col) * 4;
        sr[0] = a0 * r0[0] + a1 * r0[1] + a2 * r0[2];
        sr[1] = a0 * r1[0] + a1 * r1[1] + a2 * r1[2];
        sr[2] = a0 * r2[0] + a1 * r2[1] + a2 * r2[2];
        sr[3] = a0 + a1 + a2;
    }
    __syncthreads();

    // deterministic reduction over 7 oc-groups
    for (int idx = tid; idx < 8 * 32 * 4; idx += 224) {
        const int cch = idx & 3;
        const int col = (idx >> 2) & 31;
        const int yy  = idx >> 7;
        float v = 0.f;
        #pragma unroll
        for (int gg = 0; gg < 7; gg++) v += s_red[((gg * 8 + yy) * 32 + col) * 4 + cch];
        g_part[(size_t)(z * 4 + cch) * HWSZ + (y0 + yy) * WW + x0 + col] = v;
    }
}

// ---------------------------------------------------------------------------
__global__ __launch_bounds__(256)
void finalize_k(float* __restrict__ out)
{
    const int i = blockIdx.x * blockDim.x + threadIdx.x;
    if (i >= HWSZ) return;
    float sr = 0.f, sg = 0.f, sb = 0.f, ss = 0.f;
    for (int zz = 0; zz < 21; zz++) {
        const float* p = g_part + (size_t)(zz * 4) * HWSZ + i;
        sr += p[0];
        sg += p[(size_t)HWSZ];
        sb += p[(size_t)2 * HWSZ];
        ss += p[(size_t)3 * HWSZ];
    }
    const float inv = 1.f / (ss + 1e-6f);
    out[i]                    = sr * inv;
    out[(size_t)HWSZ + i]     = sg * inv;
    out[(size_t)2 * HWSZ + i] = sb * inv;
}

// ---------------------------------------------------------------------------
// inputs: input, ref(unused), w0, b0, w_mid, b_mid, w_last, b_last
// ---------------------------------------------------------------------------
extern "C" void kernel_launch(void* const* d_in, const int* in_sizes, int n_in,
                              void* d_out, int out_size)
{
    const float* input  = (const float*)d_in[0];
    const float* w0     = (const float*)d_in[2];
    const float* b0     = (const float*)d_in[3];
    const float* w_mid  = (const float*)d_in[4];
    const float* b_mid  = (const float*)d_in[5];
    const float* w_last = (const float*)d_in[6];
    const float* b_last = (const float*)d_in[7];
    float* out = (float*)d_out;

    cudaFuncSetAttribute(conv3x3_k<10, false>, cudaFuncAttributeMaxDynamicSharedMemorySize, C3_SMEM);
    cudaFuncSetAttribute(conv3x3_k<100, true>, cudaFuncAttributeMaxDynamicSharedMemorySize, C3_SMEM);
    cudaFuncSetAttribute(convlast_k, cudaFuncAttributeMaxDynamicSharedMemorySize, CL_SMEM);

    float *A, *B;
    cudaGetSymbolAddress((void**)&A, g_bufA);
    cudaGetSymbolAddress((void**)&B, g_bufB);

    const dim3 gc(WW / 32, HH / 16, 5);

    conv3x3_k<10, false><<<gc, 320, C3_SMEM>>>(input, w0, b0, A);

    const float* cur = A;
    float* nxt = B;
    for (int l = 0; l < 23; l++) {
        conv3x3_k<100, true><<<gc, 320, C3_SMEM>>>(cur, w_mid + (size_t)l * 90000,
                                                   b_mid + (size_t)l * 100, nxt);
        float* t = (float*)cur; cur = nxt; nxt = t;
    }

    convlast_k<<<dim3(WW / 32, HH / 8, 21), 224, CL_SMEM>>>(cur, input, w_last, b_last);

    finalize_k<<<(HWSZ + 255) / 256, 256>>>(out);
}